// round 9
// baseline (speedup 1.0000x reference)
#include <cuda_runtime.h>
#include <cuda_bf16.h>
#include <cstdint>

// ---------------------------------------------------------------------------
// GAE 4-layer GCN autoencoder: algebraic fusion + CSR gather + tf32 tensor-core
// GEMMs for the N-dominant matmuls.
//   W21 = W2 @ W1 (fp32 FFMA), W21t/head1t transposes
//   P   = X @ W21^T      (tf32 mma)   [N,128]
//   h2  = Ahat(Ahat P) + c(x)u2 + b2  (exact fp32 gather)
//   z   = h2 @ head1     (tf32 mma)
//   h4  = Ahat(Ahat z) @ W21 + c(x)u4 + b4  (tf32 mma epilogue-fused)
// ---------------------------------------------------------------------------

#define N_NODES 20000
#define IN_DIM  1024
#define HID_DIM 512
#define OUT_DIM 128
#define N_EDGES 160000

__device__ alignas(16) float g_T[(size_t)N_NODES * OUT_DIM];
__device__ alignas(16) float g_H[(size_t)N_NODES * OUT_DIM];
__device__ alignas(16) float g_W21[(size_t)OUT_DIM * IN_DIM];    // [128,1024]
__device__ alignas(16) float g_W21t[(size_t)IN_DIM * OUT_DIM];   // [1024,128]
__device__ alignas(16) float g_Ht[(size_t)OUT_DIM * OUT_DIM];    // head1^T
__device__ alignas(16) float g_u2[OUT_DIM];
__device__ alignas(16) float g_u4[IN_DIM];
__device__ float g_dinv[N_NODES];
__device__ float g_sn[N_NODES];
__device__ float g_c[N_NODES];
__device__ int   g_cnt[N_NODES];
__device__ int   g_off[N_NODES + 1];
__device__ int   g_cur[N_NODES];
__device__ int2  g_adj[N_EDGES];
__device__ int   g_is64;

// pointer selector: 0 ext, 1 g_T, 2 g_H, 3 g_W21, 4 g_W21t, 5 g_Ht
template <int SEL>
__device__ __forceinline__ float* pick(float* ext) {
    if (SEL == 1) return g_T;
    if (SEL == 2) return g_H;
    if (SEL == 3) return g_W21;
    if (SEL == 4) return g_W21t;
    if (SEL == 5) return g_Ht;
    return ext;
}
template <int SEL>
__device__ __forceinline__ const float* pickc(const float* ext) {
    if (SEL == 1) return g_T;
    if (SEL == 2) return g_H;
    if (SEL == 3) return g_W21;
    if (SEL == 4) return g_W21t;
    if (SEL == 5) return g_Ht;
    return ext;
}

__device__ __forceinline__ unsigned f2t(float x) {
    unsigned u;
    asm("cvt.rna.tf32.f32 %0, %1;" : "=r"(u) : "f"(x));
    return u;
}

// ---------------------------------------------------------------------------
// Edge-index dtype probe
// ---------------------------------------------------------------------------
__global__ void k_probe_dtype(const int* __restrict__ ei32) {
    if (threadIdx.x == 0 && blockIdx.x == 0) {
        int z = (ei32[1] == 0) & (ei32[3] == 0) & (ei32[5] == 0) &
                (ei32[7] == 0) & (ei32[9] == 0) & (ei32[11] == 0);
        g_is64 = z;
    }
}

__device__ __forceinline__ int load_idx(const void* ei, int e_cnt, int row, int e) {
    if (g_is64) return (int)((const long long*)ei)[(size_t)row * e_cnt + e];
    return ((const int*)ei)[(size_t)row * e_cnt + e];
}

// ---------------------------------------------------------------------------
// CSR build
// ---------------------------------------------------------------------------
__global__ void k_zero_cnt(int n) {
    int i = blockIdx.x * blockDim.x + threadIdx.x;
    if (i < n) g_cnt[i] = 0;
}

__global__ void k_count(const void* __restrict__ ei, int e_cnt, int n) {
    int e = blockIdx.x * blockDim.x + threadIdx.x;
    if (e < e_cnt) {
        int d = load_idx(ei, e_cnt, 1, e);
        if ((unsigned)d < (unsigned)n) atomicAdd(&g_cnt[d], 1);
    }
}

__global__ void k_dinv(int n) {
    int i = blockIdx.x * blockDim.x + threadIdx.x;
    if (i < n) {
        float r = rsqrtf((float)(g_cnt[i] + 1));
        g_dinv[i] = r;
        g_sn[i] = r * r;
    }
}

__global__ void k_scan(int n) {
    __shared__ int sh[1024];
    __shared__ int carry_s;
    int tid = threadIdx.x;
    if (tid == 0) { carry_s = 0; g_off[0] = 0; }
    __syncthreads();
    for (int base = 0; base < n; base += 1024) {
        int i = base + tid;
        int v = (i < n) ? g_cnt[i] : 0;
        sh[tid] = v;
        __syncthreads();
        for (int s = 1; s < 1024; s <<= 1) {
            int t = (tid >= s) ? sh[tid - s] : 0;
            __syncthreads();
            sh[tid] += t;
            __syncthreads();
        }
        int carry = carry_s;
        if (i < n) {
            g_off[i + 1] = carry + sh[tid];
            g_cur[i]     = carry + sh[tid] - v;
        }
        __syncthreads();
        if (tid == 0) carry_s = carry + sh[1023];
        __syncthreads();
    }
}

__global__ void k_fill(const void* __restrict__ ei, int e_cnt, int n) {
    int e = blockIdx.x * blockDim.x + threadIdx.x;
    if (e < e_cnt) {
        int s = load_idx(ei, e_cnt, 0, e);
        int d = load_idx(ei, e_cnt, 1, e);
        if ((unsigned)s >= (unsigned)n) s = 0;
        if ((unsigned)d >= (unsigned)n) d = 0;
        float w = g_dinv[s] * g_dinv[d];
        int pos = atomicAdd(&g_cur[d], 1);
        g_adj[pos] = make_int2(s, __float_as_int(w));
    }
}

__global__ void k_c(int n) {
    int i = blockIdx.x * blockDim.x + threadIdx.x;
    if (i < n) {
        float acc = g_sn[i];
        int beg = g_off[i], end = g_off[i + 1];
        for (int p = beg; p < end; p++) acc += __int_as_float(g_adj[p].y);
        g_c[i] = acc;
    }
}

// ---------------------------------------------------------------------------
// Small precomputes
// ---------------------------------------------------------------------------
__global__ void k_u2(const float* __restrict__ W2, const float* __restrict__ b1) {
    int o = blockIdx.x * blockDim.x + threadIdx.x;
    if (o < OUT_DIM) {
        float s = 0.f;
        for (int k = 0; k < HID_DIM; k++) s += W2[(size_t)o * HID_DIM + k] * b1[k];
        g_u2[o] = s;
    }
}

__global__ void k_u4(const float* __restrict__ W1, const float* __restrict__ b3) {
    int f = blockIdx.x * blockDim.x + threadIdx.x;
    if (f < IN_DIM) {
        float s = 0.f;
        for (int k = 0; k < HID_DIM; k++) s += b3[k] * W1[(size_t)k * IN_DIM + f];
        g_u4[f] = s;
    }
}

// ---------------------------------------------------------------------------
// Tiled transpose: D[c][r] = S[r][c]
// ---------------------------------------------------------------------------
template <int SSEL, int DSEL>
__global__ void k_transpose(const float* __restrict__ Sext,
                            float* __restrict__ Dext,
                            int rows, int cols) {
    const float* S = pickc<SSEL>(Sext);
    float*       D = pick<DSEL>(Dext);
    __shared__ float tile[32][33];
    int rc = blockIdx.y * 32, cc = blockIdx.x * 32;
    int tx = threadIdx.x, ty = threadIdx.y;
#pragma unroll
    for (int k = 0; k < 4; k++) {
        int r = rc + ty + k * 8, c = cc + tx;
        if (r < rows && c < cols) tile[ty + k * 8][tx] = S[(size_t)r * cols + c];
    }
    __syncthreads();
#pragma unroll
    for (int k = 0; k < 4; k++) {
        int c = cc + ty + k * 8, r = rc + tx;
        if (r < rows && c < cols) D[(size_t)c * rows + r] = tile[tx][ty + k * 8];
    }
}

// ---------------------------------------------------------------------------
// FFMA SGEMM (only for W21 = W2 @ W1, exact fp32; M=128 exact multiple of 64)
//   C = A[M,K] @ B[K,Nn], C -> g_W21. BM=64, BN=128, BK=8.
// ---------------------------------------------------------------------------
__global__ __launch_bounds__(256)
void k_w21(const float* __restrict__ A, const float* __restrict__ B) {
    __shared__ float As[8][64];
    __shared__ float Bs[8][128];
    const int bx = blockIdx.x;
    const int by = blockIdx.y;
    const int tid = threadIdx.x;
    const int tcol = tid % 16;
    const int trow = tid / 16;

    float acc[4][8];
#pragma unroll
    for (int i = 0; i < 4; i++)
#pragma unroll
        for (int j = 0; j < 8; j++) acc[i][j] = 0.0f;

    for (int k0 = 0; k0 < HID_DIM; k0 += 8) {
        if (tid < 128) {
            int aRow = tid >> 1;
            int aCol = (tid & 1) << 2;
            int m = by * 64 + aRow;
            float4 av = *(const float4*)(A + (size_t)m * HID_DIM + k0 + aCol);
            As[aCol + 0][aRow] = av.x;
            As[aCol + 1][aRow] = av.y;
            As[aCol + 2][aRow] = av.z;
            As[aCol + 3][aRow] = av.w;
        }
        {
            int kk = tid >> 5;
            int nn = (tid & 31) << 2;
            float4 bv = *(const float4*)(B + (size_t)(k0 + kk) * IN_DIM + bx * 128 + nn);
            *(float4*)&Bs[kk][nn] = bv;
        }
        __syncthreads();
#pragma unroll
        for (int k = 0; k < 8; k++) {
            float ra[4], rb[8];
#pragma unroll
            for (int i = 0; i < 4; i++) ra[i] = As[k][trow * 4 + i];
#pragma unroll
            for (int j = 0; j < 8; j++) rb[j] = Bs[k][tcol * 8 + j];
#pragma unroll
            for (int i = 0; i < 4; i++)
#pragma unroll
                for (int j = 0; j < 8; j++) acc[i][j] += ra[i] * rb[j];
        }
        __syncthreads();
    }
#pragma unroll
    for (int i = 0; i < 4; i++) {
        int m = by * 64 + trow * 4 + i;
        float* cp = g_W21 + (size_t)m * IN_DIM + bx * 128 + tcol * 8;
        *(float4*)(cp + 0) = make_float4(acc[i][0], acc[i][1], acc[i][2], acc[i][3]);
        *(float4*)(cp + 4) = make_float4(acc[i][4], acc[i][5], acc[i][6], acc[i][7]);
    }
}

// ---------------------------------------------------------------------------
// tf32 tensor-core GEMM (TN form):
//   C[M,Nn] = A[M,K] @ B'[K,Nn], where B is stored [Nn,K] row-major.
//   + bias[n] (if bias) + CORR4 (c[m]*u4[n]).
// BMv in {64,128}, BN=128, BK=32, 256 threads (8 warps, warp grid 2m x 4n).
// K % 32 == 0, Nn % 128 == 0, M guarded.
// ---------------------------------------------------------------------------
template <int ASEL, int BSEL, int CSEL, int CORR4, int BMv>
__global__ __launch_bounds__(256)
void k_mma(int M, int Nn, int K,
           const float* __restrict__ Aext,
           const float* __restrict__ Bext,
           float* __restrict__ Cext,
           const float* __restrict__ bias) {
    constexpr int MT = BMv / 32;        // m16-tiles per warp (2 or 4)
    const float* A = pickc<ASEL>(Aext);
    const float* B = pickc<BSEL>(Bext);
    float*       C = pick<CSEL>(Cext);

    __shared__ float As[BMv][36];
    __shared__ float Bs[128][36];

    const int tid  = threadIdx.x;
    const int lane = tid & 31;
    const int wid  = tid >> 5;
    const int g    = lane >> 2;   // 0..7
    const int t    = lane & 3;    // 0..3
    const int wm   = (wid & 1) * (BMv / 2);
    const int wn   = (wid >> 1) * 32;
    const int bx   = blockIdx.x;
    const int by   = blockIdx.y;

    float c[MT][4][4];
#pragma unroll
    for (int i = 0; i < MT; i++)
#pragma unroll
        for (int j = 0; j < 4; j++)
#pragma unroll
            for (int r = 0; r < 4; r++) c[i][j][r] = 0.0f;

    for (int k0 = 0; k0 < K; k0 += 32) {
        // --- load A tile: BMv x 32 (cvt to tf32) ---
#pragma unroll
        for (int i = 0; i < BMv / 32; i++) {
            int f4 = tid + i * 256;
            int m  = f4 >> 3;
            int kq = (f4 & 7) << 2;
            int gm = by * BMv + m;
            float4 v = make_float4(0.f, 0.f, 0.f, 0.f);
            if (gm < M) v = *(const float4*)(A + (size_t)gm * K + k0 + kq);
            float4 w;
            w.x = __uint_as_float(f2t(v.x));
            w.y = __uint_as_float(f2t(v.y));
            w.z = __uint_as_float(f2t(v.z));
            w.w = __uint_as_float(f2t(v.w));
            *(float4*)&As[m][kq] = w;
        }
        // --- load B tile: 128 x 32 (B is [Nn,K] n-major) ---
#pragma unroll
        for (int i = 0; i < 4; i++) {
            int f4 = tid + i * 256;
            int nn = f4 >> 3;
            int kq = (f4 & 7) << 2;
            float4 v = *(const float4*)(B + (size_t)(bx * 128 + nn) * K + k0 + kq);
            float4 w;
            w.x = __uint_as_float(f2t(v.x));
            w.y = __uint_as_float(f2t(v.y));
            w.z = __uint_as_float(f2t(v.z));
            w.w = __uint_as_float(f2t(v.w));
            *(float4*)&Bs[nn][kq] = w;
        }
        __syncthreads();

#pragma unroll
        for (int ks = 0; ks < 4; ks++) {
            unsigned a[MT][4], b[4][2];
            int kk = ks * 8 + t;
#pragma unroll
            for (int i = 0; i < MT; i++) {
                int mr = wm + i * 16 + g;
                a[i][0] = __float_as_uint(As[mr    ][kk    ]);
                a[i][1] = __float_as_uint(As[mr + 8][kk    ]);
                a[i][2] = __float_as_uint(As[mr    ][kk + 4]);
                a[i][3] = __float_as_uint(As[mr + 8][kk + 4]);
            }
#pragma unroll
            for (int j = 0; j < 4; j++) {
                int nr = wn + j * 8 + g;
                b[j][0] = __float_as_uint(Bs[nr][kk    ]);
                b[j][1] = __float_as_uint(Bs[nr][kk + 4]);
            }
#pragma unroll
            for (int i = 0; i < MT; i++)
#pragma unroll
                for (int j = 0; j < 4; j++) {
                    asm volatile(
                        "mma.sync.aligned.m16n8k8.row.col.f32.tf32.tf32.f32 "
                        "{%0,%1,%2,%3}, {%4,%5,%6,%7}, {%8,%9}, {%0,%1,%2,%3};"
                        : "+f"(c[i][j][0]), "+f"(c[i][j][1]),
                          "+f"(c[i][j][2]), "+f"(c[i][j][3])
                        : "r"(a[i][0]), "r"(a[i][1]), "r"(a[i][2]), "r"(a[i][3]),
                          "r"(b[j][0]), "r"(b[j][1]));
                }
        }
        __syncthreads();
    }

    // --- epilogue ---
#pragma unroll
    for (int j = 0; j < 4; j++) {
        int cn = bx * 128 + wn + j * 8 + t * 2;
        float e0 = bias ? bias[cn]     : 0.0f;
        float e1 = bias ? bias[cn + 1] : 0.0f;
        float u40 = CORR4 ? g_u4[cn]     : 0.0f;
        float u41 = CORR4 ? g_u4[cn + 1] : 0.0f;
#pragma unroll
        for (int i = 0; i < MT; i++) {
            int r0 = by * BMv + wm + i * 16 + g;
            if (r0 < M) {
                float a0 = c[i][j][0] + e0, a1 = c[i][j][1] + e1;
                if (CORR4) { float ci = g_c[r0]; a0 += ci * u40; a1 += ci * u41; }
                *(float2*)(C + (size_t)r0 * Nn + cn) = make_float2(a0, a1);
            }
            int r1 = r0 + 8;
            if (r1 < M) {
                float a2 = c[i][j][2] + e0, a3 = c[i][j][3] + e1;
                if (CORR4) { float ci = g_c[r1]; a2 += ci * u40; a3 += ci * u41; }
                *(float2*)(C + (size_t)r1 * Nn + cn) = make_float2(a2, a3);
            }
        }
    }
}

// ---------------------------------------------------------------------------
// Aggregation (warp-per-node CSR gather), width 128 — exact fp32
// ---------------------------------------------------------------------------
template <int SSEL, int DSEL, int CORR>
__global__ __launch_bounds__(256)
void k_agg(const float* __restrict__ Sext,
           float* __restrict__ Dext,
           const float* __restrict__ b,
           int n) {
    int gw = (blockIdx.x * 256 + threadIdx.x) >> 5;
    if (gw >= n) return;
    int lane = threadIdx.x & 31;
    const float* S = pickc<SSEL>(Sext);
    float*       D = pick<DSEL>(Dext);

    int beg = g_off[gw];
    int end = g_off[gw + 1];
    float sn = g_sn[gw];
    float4 v = *(const float4*)(S + (size_t)gw * OUT_DIM + lane * 4);
    float4 acc = make_float4(sn * v.x, sn * v.y, sn * v.z, sn * v.w);

    for (int p = beg; p < end; p++) {
        int2 pr = g_adj[p];
        float w = __int_as_float(pr.y);
        float4 u = *(const float4*)(S + (size_t)pr.x * OUT_DIM + lane * 4);
        acc.x += w * u.x;
        acc.y += w * u.y;
        acc.z += w * u.z;
        acc.w += w * u.w;
    }

    if (CORR) {
        float ci = g_c[gw];
        int f = lane * 4;
        acc.x += ci * g_u2[f + 0] + b[f + 0];
        acc.y += ci * g_u2[f + 1] + b[f + 1];
        acc.z += ci * g_u2[f + 2] + b[f + 2];
        acc.w += ci * g_u2[f + 3] + b[f + 3];
    }
    *(float4*)(D + (size_t)gw * OUT_DIM + lane * 4) = acc;
}

// ---------------------------------------------------------------------------
static inline int ceil_div(int a, int b) { return (a + b - 1) / b; }

extern "C" void kernel_launch(void* const* d_in, const int* in_sizes, int n_in,
                              void* d_out, int out_size) {
    const float* features = (const float*)d_in[0];   // [N,1024]
    const void*  edge_idx = d_in[1];                 // [2,E]
    const float* W1       = (const float*)d_in[2];   // [512,1024]
    const float* b1       = (const float*)d_in[3];
    const float* W2       = (const float*)d_in[4];   // [128,512]
    const float* b2       = (const float*)d_in[5];
    const float* b3       = (const float*)d_in[6];
    const float* b4       = (const float*)d_in[7];
    const float* head1    = (const float*)d_in[8];   // [128,128]

    const int n = in_sizes[0] / IN_DIM;
    const int e = in_sizes[1] / 2;

    float* out = (float*)d_out;
    float* z_out  = out;
    float* h2_out = out + (size_t)n * OUT_DIM;
    float* h4_out = out + (size_t)n * OUT_DIM * 2;

    const int TPB = 256;
    dim3 blk(256);
    int aggb = ceil_div(n * 32, TPB);

    // ---- CSR + norm preprocessing ----
    k_probe_dtype<<<1, 32>>>((const int*)edge_idx);
    k_zero_cnt<<<ceil_div(n, TPB), TPB>>>(n);
    k_count<<<ceil_div(e, TPB), TPB>>>(edge_idx, e, n);
    k_dinv<<<ceil_div(n, TPB), TPB>>>(n);
    k_scan<<<1, 1024>>>(n);
    k_fill<<<ceil_div(e, TPB), TPB>>>(edge_idx, e, n);
    k_c<<<ceil_div(n, TPB), TPB>>>(n);

    // ---- weight precomputes ----
    {
        dim3 grid(IN_DIM / 128, 2);   // W21 = W2 @ W1 (fp32), M=128 in 2x BM=64
        k_w21<<<grid, blk>>>(W2, W1);
        k_u2<<<1, 128>>>(W2, b1);
        k_u4<<<ceil_div(IN_DIM, TPB), TPB>>>(W1, b3);
        dim3 tb(32, 8);
        dim3 tg1(IN_DIM / 32, OUT_DIM / 32);
        k_transpose<3, 4><<<tg1, tb>>>(nullptr, nullptr, OUT_DIM, IN_DIM);   // W21 -> W21t
        dim3 tg2(OUT_DIM / 32, OUT_DIM / 32);
        k_transpose<0, 5><<<tg2, tb>>>(head1, nullptr, OUT_DIM, OUT_DIM);    // head1 -> Ht
    }

    // ---- P = X @ W21^T [N,128] -> g_T (tf32) ----
    {
        dim3 grid(1, ceil_div(n, 64));
        k_mma<0, 3, 1, 0, 64><<<grid, blk>>>(n, OUT_DIM, IN_DIM, features, nullptr, nullptr, nullptr);
    }

    // ---- S1 = Ahat P -> g_H ;  h2 = Ahat S1 + c(x)u2 + b2 -> h2_out ----
    k_agg<1, 2, 0><<<aggb, blk>>>(nullptr, nullptr, nullptr, n);
    k_agg<2, 0, 1><<<aggb, blk>>>(nullptr, h2_out, b2, n);

    // ---- z = h2 @ head1 -> z_out (tf32, B = head1^T) ----
    {
        dim3 grid(1, ceil_div(n, 64));
        k_mma<0, 5, 0, 0, 64><<<grid, blk>>>(n, OUT_DIM, OUT_DIM, h2_out, nullptr, z_out, nullptr);
    }

    // ---- S2 = Ahat z -> g_T ;  Q = Ahat S2 -> g_H ----
    k_agg<0, 1, 0><<<aggb, blk>>>(z_out, nullptr, nullptr, n);
    k_agg<1, 2, 0><<<aggb, blk>>>(nullptr, nullptr, nullptr, n);

    // ---- h4 = Q @ W21 + c(x)u4 + b4 -> h4_out (tf32, B = W21t) ----
    {
        dim3 grid(IN_DIM / 128, ceil_div(n, 128));
        k_mma<2, 4, 0, 1, 128><<<grid, blk>>>(n, IN_DIM, OUT_DIM, nullptr, nullptr, h4_out, b4);
    }

    (void)n_in; (void)out_size;
}

// round 10
// speedup vs baseline: 1.0421x; 1.0421x over previous
#include <cuda_runtime.h>
#include <cuda_bf16.h>
#include <cstdint>

// ---------------------------------------------------------------------------
// GAE 4-layer GCN autoencoder: algebraic fusion + CSR gather + tf32 mma GEMMs
// with register-prefetch pipelining and pre-rounded tf32 B operands.
// ---------------------------------------------------------------------------

#define N_NODES 20000
#define IN_DIM  1024
#define HID_DIM 512
#define OUT_DIM 128
#define N_EDGES 160000

__device__ alignas(16) float g_T[(size_t)N_NODES * OUT_DIM];
__device__ alignas(16) float g_H[(size_t)N_NODES * OUT_DIM];
__device__ alignas(16) float g_W21[(size_t)OUT_DIM * IN_DIM];    // [128,1024] tf32-rounded
__device__ alignas(16) float g_W21t[(size_t)IN_DIM * OUT_DIM];   // [1024,128] tf32-rounded
__device__ alignas(16) float g_Ht[(size_t)OUT_DIM * OUT_DIM];    // head1^T tf32-rounded
__device__ alignas(16) float g_u2[OUT_DIM];
__device__ alignas(16) float g_u4[IN_DIM];
__device__ float g_dinv[N_NODES];
__device__ float g_sn[N_NODES];
__device__ float g_c[N_NODES];
__device__ int   g_cnt[N_NODES];
__device__ int   g_off[N_NODES + 1];
__device__ int   g_cur[N_NODES];
__device__ int2  g_adj[N_EDGES];
__device__ int   g_is64;

// pointer selector: 0 ext, 1 g_T, 2 g_H, 3 g_W21, 4 g_W21t, 5 g_Ht
template <int SEL>
__device__ __forceinline__ float* pick(float* ext) {
    if (SEL == 1) return g_T;
    if (SEL == 2) return g_H;
    if (SEL == 3) return g_W21;
    if (SEL == 4) return g_W21t;
    if (SEL == 5) return g_Ht;
    return ext;
}
template <int SEL>
__device__ __forceinline__ const float* pickc(const float* ext) {
    if (SEL == 1) return g_T;
    if (SEL == 2) return g_H;
    if (SEL == 3) return g_W21;
    if (SEL == 4) return g_W21t;
    if (SEL == 5) return g_Ht;
    return ext;
}

__device__ __forceinline__ unsigned f2t(float x) {
    unsigned u;
    asm("cvt.rna.tf32.f32 %0, %1;" : "=r"(u) : "f"(x));
    return u;
}
__device__ __forceinline__ float f2tf(float x) { return __uint_as_float(f2t(x)); }

// ---------------------------------------------------------------------------
// probe dtype + zero counters (fused)
// ---------------------------------------------------------------------------
__global__ void k_pre(const int* __restrict__ ei32, int n) {
    int i = blockIdx.x * blockDim.x + threadIdx.x;
    if (i == 0) {
        int z = (ei32[1] == 0) & (ei32[3] == 0) & (ei32[5] == 0) &
                (ei32[7] == 0) & (ei32[9] == 0) & (ei32[11] == 0);
        g_is64 = z;
    }
    if (i < n) g_cnt[i] = 0;
}

__device__ __forceinline__ int load_idx(const void* ei, int e_cnt, int row, int e) {
    if (g_is64) return (int)((const long long*)ei)[(size_t)row * e_cnt + e];
    return ((const int*)ei)[(size_t)row * e_cnt + e];
}

__global__ void k_count(const void* __restrict__ ei, int e_cnt, int n) {
    int e = blockIdx.x * blockDim.x + threadIdx.x;
    if (e < e_cnt) {
        int d = load_idx(ei, e_cnt, 1, e);
        if ((unsigned)d < (unsigned)n) atomicAdd(&g_cnt[d], 1);
    }
}

__global__ void k_dinv(int n) {
    int i = blockIdx.x * blockDim.x + threadIdx.x;
    if (i < n) {
        float r = rsqrtf((float)(g_cnt[i] + 1));
        g_dinv[i] = r;
        g_sn[i] = r * r;
    }
}

// single-block warp-shuffle exclusive scan of g_cnt -> g_off (+ g_cur)
__global__ void k_scan(int n) {
    __shared__ int ws[32];
    __shared__ int carry_sh;
    int tid = threadIdx.x, lane = tid & 31, wid = tid >> 5;
    if (tid == 0) { carry_sh = 0; g_off[0] = 0; }
    __syncthreads();
    for (int base = 0; base < n; base += 1024) {
        int i = base + tid;
        int v = (i < n) ? g_cnt[i] : 0;
        int x = v;
#pragma unroll
        for (int s = 1; s < 32; s <<= 1) {
            int y = __shfl_up_sync(0xFFFFFFFFu, x, s);
            if (lane >= s) x += y;
        }
        if (lane == 31) ws[wid] = x;
        __syncthreads();
        if (wid == 0) {
            int w = ws[lane];
#pragma unroll
            for (int s = 1; s < 32; s <<= 1) {
                int y = __shfl_up_sync(0xFFFFFFFFu, w, s);
                if (lane >= s) w += y;
            }
            ws[lane] = w;
        }
        __syncthreads();
        int carry = carry_sh;
        int woff = (wid > 0) ? ws[wid - 1] : 0;
        int incl = carry + woff + x;
        if (i < n) {
            g_off[i + 1] = incl;
            g_cur[i]     = incl - v;
        }
        __syncthreads();
        if (tid == 1023) carry_sh = carry + ws[31];
        __syncthreads();
    }
}

__global__ void k_fill(const void* __restrict__ ei, int e_cnt, int n) {
    int e = blockIdx.x * blockDim.x + threadIdx.x;
    if (e < e_cnt) {
        int s = load_idx(ei, e_cnt, 0, e);
        int d = load_idx(ei, e_cnt, 1, e);
        if ((unsigned)s >= (unsigned)n) s = 0;
        if ((unsigned)d >= (unsigned)n) d = 0;
        float w = g_dinv[s] * g_dinv[d];
        int pos = atomicAdd(&g_cur[d], 1);
        g_adj[pos] = make_int2(s, __float_as_int(w));
    }
}

// ---------------------------------------------------------------------------
// misc precomputes: u4 (blocks 0..3), u2 (block 4), head1^T tf32 (block 5)
// ---------------------------------------------------------------------------
__global__ void k_misc(const float* __restrict__ W1, const float* __restrict__ W2,
                       const float* __restrict__ b1, const float* __restrict__ b3,
                       const float* __restrict__ head1) {
    int bidx = blockIdx.x;
    if (bidx < 4) {
        int f = bidx * 256 + threadIdx.x;
        float s = 0.f;
        for (int k = 0; k < HID_DIM; k++) s += b3[k] * W1[(size_t)k * IN_DIM + f];
        g_u4[f] = s;
    } else if (bidx == 4) {
        if (threadIdx.x < OUT_DIM) {
            int o = threadIdx.x;
            float s = 0.f;
            for (int k = 0; k < HID_DIM; k++) s += W2[(size_t)o * HID_DIM + k] * b1[k];
            g_u2[o] = s;
        }
    } else {
        for (int idx = threadIdx.x; idx < OUT_DIM * OUT_DIM; idx += 256) {
            int r = idx >> 7, c = idx & 127;
            g_Ht[(size_t)c * OUT_DIM + r] = f2tf(head1[idx]);
        }
    }
}

// ---------------------------------------------------------------------------
// W21 = W2 @ W1 (fp32 FFMA), epilogue writes tf32-rounded W21 and W21^T.
// grid (IN_DIM/128, 2), BM=64, BN=128, BK=8, 256 threads.
// ---------------------------------------------------------------------------
__global__ __launch_bounds__(256)
void k_w21(const float* __restrict__ A, const float* __restrict__ B) {
    __shared__ float As[8][64];
    __shared__ float Bs[8][128];
    const int bx = blockIdx.x;
    const int by = blockIdx.y;
    const int tid = threadIdx.x;
    const int tcol = tid % 16;
    const int trow = tid / 16;

    float acc[4][8];
#pragma unroll
    for (int i = 0; i < 4; i++)
#pragma unroll
        for (int j = 0; j < 8; j++) acc[i][j] = 0.0f;

    for (int k0 = 0; k0 < HID_DIM; k0 += 8) {
        if (tid < 128) {
            int aRow = tid >> 1;
            int aCol = (tid & 1) << 2;
            int m = by * 64 + aRow;
            float4 av = *(const float4*)(A + (size_t)m * HID_DIM + k0 + aCol);
            As[aCol + 0][aRow] = av.x;
            As[aCol + 1][aRow] = av.y;
            As[aCol + 2][aRow] = av.z;
            As[aCol + 3][aRow] = av.w;
        }
        {
            int kk = tid >> 5;
            int nn = (tid & 31) << 2;
            float4 bv = *(const float4*)(B + (size_t)(k0 + kk) * IN_DIM + bx * 128 + nn);
            *(float4*)&Bs[kk][nn] = bv;
        }
        __syncthreads();
#pragma unroll
        for (int k = 0; k < 8; k++) {
            float ra[4], rb[8];
#pragma unroll
            for (int i = 0; i < 4; i++) ra[i] = As[k][trow * 4 + i];
#pragma unroll
            for (int j = 0; j < 8; j++) rb[j] = Bs[k][tcol * 8 + j];
#pragma unroll
            for (int i = 0; i < 4; i++)
#pragma unroll
                for (int j = 0; j < 8; j++) acc[i][j] += ra[i] * rb[j];
        }
        __syncthreads();
    }
#pragma unroll
    for (int i = 0; i < 4; i++) {
        int m = by * 64 + trow * 4 + i;
#pragma unroll
        for (int j = 0; j < 8; j++) {
            int col = bx * 128 + tcol * 8 + j;
            float w = f2tf(acc[i][j]);
            g_W21[(size_t)m * IN_DIM + col]  = w;
            g_W21t[(size_t)col * OUT_DIM + m] = w;
        }
    }
}

// ---------------------------------------------------------------------------
// tf32 tensor-core GEMM (TN form), register-prefetch pipelined.
//   C[M,Nn] = A[M,K] @ B'[K,Nn], B stored [Nn,K] n-major, PRE-ROUNDED tf32.
//   A converted to tf32 on the smem store path.
//   + bias[n] + CORR4 (c[m]*u4[n]). BMv in {64,128}, BN=128, BK=32, 8 warps.
// ---------------------------------------------------------------------------
template <int ASEL, int BSEL, int CSEL, int CORR4, int BMv>
__global__ __launch_bounds__(256)
void k_mma(int M, int Nn, int K,
           const float* __restrict__ Aext,
           const float* __restrict__ Bext,
           float* __restrict__ Cext,
           const float* __restrict__ bias) {
    constexpr int MT  = BMv / 32;
    constexpr int AR4 = (BMv * 32) / (256 * 4);   // float4 per thread for A tile
    const float* A = pickc<ASEL>(Aext);
    const float* B = pickc<BSEL>(Bext);
    float*       C = pick<CSEL>(Cext);

    __shared__ float As[BMv][36];
    __shared__ float Bs[128][36];

    const int tid  = threadIdx.x;
    const int lane = tid & 31;
    const int wid  = tid >> 5;
    const int g    = lane >> 2;
    const int t    = lane & 3;
    const int wm   = (wid & 1) * (BMv / 2);
    const int wn   = (wid >> 1) * 32;
    const int bx   = blockIdx.x;
    const int by   = blockIdx.y;

    float4 ar[AR4], br[4];

    auto loadA = [&](int k0) {
#pragma unroll
        for (int i = 0; i < AR4; i++) {
            int f4 = tid + i * 256;
            int m  = f4 >> 3;
            int kq = (f4 & 7) << 2;
            int gm = by * BMv + m;
            ar[i] = (gm < M) ? *(const float4*)(A + (size_t)gm * K + k0 + kq)
                             : make_float4(0.f, 0.f, 0.f, 0.f);
        }
    };
    auto loadB = [&](int k0) {
#pragma unroll
        for (int i = 0; i < 4; i++) {
            int f4 = tid + i * 256;
            int nn = f4 >> 3;
            int kq = (f4 & 7) << 2;
            br[i] = *(const float4*)(B + (size_t)(bx * 128 + nn) * K + k0 + kq);
        }
    };
    auto storeA = [&]() {
#pragma unroll
        for (int i = 0; i < AR4; i++) {
            int f4 = tid + i * 256;
            int m  = f4 >> 3;
            int kq = (f4 & 7) << 2;
            float4 w;
            w.x = f2tf(ar[i].x); w.y = f2tf(ar[i].y);
            w.z = f2tf(ar[i].z); w.w = f2tf(ar[i].w);
            *(float4*)&As[m][kq] = w;
        }
    };
    auto storeB = [&]() {
#pragma unroll
        for (int i = 0; i < 4; i++) {
            int f4 = tid + i * 256;
            int nn = f4 >> 3;
            int kq = (f4 & 7) << 2;
            *(float4*)&Bs[nn][kq] = br[i];
        }
    };

    float c[MT][4][4];
#pragma unroll
    for (int i = 0; i < MT; i++)
#pragma unroll
        for (int j = 0; j < 4; j++)
#pragma unroll
            for (int r = 0; r < 4; r++) c[i][j][r] = 0.0f;

    const int nt = K / 32;
    loadA(0); loadB(0);
    storeA(); storeB();
    __syncthreads();

    for (int it = 0; it < nt; it++) {
        if (it + 1 < nt) { loadA((it + 1) * 32); loadB((it + 1) * 32); }

#pragma unroll
        for (int ks = 0; ks < 4; ks++) {
            unsigned a[MT][4], b[4][2];
            int kk = ks * 8 + t;
#pragma unroll
            for (int i = 0; i < MT; i++) {
                int mr = wm + i * 16 + g;
                a[i][0] = __float_as_uint(As[mr    ][kk    ]);
                a[i][1] = __float_as_uint(As[mr + 8][kk    ]);
                a[i][2] = __float_as_uint(As[mr    ][kk + 4]);
                a[i][3] = __float_as_uint(As[mr + 8][kk + 4]);
            }
#pragma unroll
            for (int j = 0; j < 4; j++) {
                int nr = wn + j * 8 + g;
                b[j][0] = __float_as_uint(Bs[nr][kk    ]);
                b[j][1] = __float_as_uint(Bs[nr][kk + 4]);
            }
#pragma unroll
            for (int i = 0; i < MT; i++)
#pragma unroll
                for (int j = 0; j < 4; j++) {
                    asm volatile(
                        "mma.sync.aligned.m16n8k8.row.col.f32.tf32.tf32.f32 "
                        "{%0,%1,%2,%3}, {%4,%5,%6,%7}, {%8,%9}, {%0,%1,%2,%3};"
                        : "+f"(c[i][j][0]), "+f"(c[i][j][1]),
                          "+f"(c[i][j][2]), "+f"(c[i][j][3])
                        : "r"(a[i][0]), "r"(a[i][1]), "r"(a[i][2]), "r"(a[i][3]),
                          "r"(b[j][0]), "r"(b[j][1]));
                }
        }
        __syncthreads();
        if (it + 1 < nt) {
            storeA(); storeB();
            __syncthreads();
        }
    }

    // --- epilogue ---
#pragma unroll
    for (int j = 0; j < 4; j++) {
        int cn = bx * 128 + wn + j * 8 + t * 2;
        float e0 = bias ? bias[cn]     : 0.0f;
        float e1 = bias ? bias[cn + 1] : 0.0f;
        float u40 = CORR4 ? g_u4[cn]     : 0.0f;
        float u41 = CORR4 ? g_u4[cn + 1] : 0.0f;
#pragma unroll
        for (int i = 0; i < MT; i++) {
            int r0 = by * BMv + wm + i * 16 + g;
            if (r0 < M) {
                float a0 = c[i][j][0] + e0, a1 = c[i][j][1] + e1;
                if (CORR4) { float ci = g_c[r0]; a0 += ci * u40; a1 += ci * u41; }
                *(float2*)(C + (size_t)r0 * Nn + cn) = make_float2(a0, a1);
            }
            int r1 = r0 + 8;
            if (r1 < M) {
                float a2 = c[i][j][2] + e0, a3 = c[i][j][3] + e1;
                if (CORR4) { float ci = g_c[r1]; a2 += ci * u40; a3 += ci * u41; }
                *(float2*)(C + (size_t)r1 * Nn + cn) = make_float2(a2, a3);
            }
        }
    }
}

// ---------------------------------------------------------------------------
// Aggregation (warp-per-node CSR gather), exact fp32.
//   WRC=1: also writes g_c[i] = sn[i] + sum w  (lane 0)
//   CORR=1: adds c[i]*u2[f] + b[f]
// ---------------------------------------------------------------------------
template <int SSEL, int DSEL, int CORR, int WRC>
__global__ __launch_bounds__(256)
void k_agg(const float* __restrict__ Sext,
           float* __restrict__ Dext,
           const float* __restrict__ b,
           int n) {
    int gw = (blockIdx.x * 256 + threadIdx.x) >> 5;
    if (gw >= n) return;
    int lane = threadIdx.x & 31;
    const float* S = pickc<SSEL>(Sext);
    float*       D = pick<DSEL>(Dext);

    int beg = g_off[gw];
    int end = g_off[gw + 1];
    float sn = g_sn[gw];
    float4 v = *(const float4*)(S + (size_t)gw * OUT_DIM + lane * 4);
    float4 acc = make_float4(sn * v.x, sn * v.y, sn * v.z, sn * v.w);
    float cacc = sn;

    for (int p = beg; p < end; p++) {
        int2 pr = g_adj[p];
        float w = __int_as_float(pr.y);
        if (WRC) cacc += w;
        float4 u = *(const float4*)(S + (size_t)pr.x * OUT_DIM + lane * 4);
        acc.x += w * u.x;
        acc.y += w * u.y;
        acc.z += w * u.z;
        acc.w += w * u.w;
    }

    if (WRC && lane == 0) g_c[gw] = cacc;

    if (CORR) {
        float ci = g_c[gw];
        int f = lane * 4;
        acc.x += ci * g_u2[f + 0] + b[f + 0];
        acc.y += ci * g_u2[f + 1] + b[f + 1];
        acc.z += ci * g_u2[f + 2] + b[f + 2];
        acc.w += ci * g_u2[f + 3] + b[f + 3];
    }
    *(float4*)(D + (size_t)gw * OUT_DIM + lane * 4) = acc;
}

// ---------------------------------------------------------------------------
static inline int ceil_div(int a, int b) { return (a + b - 1) / b; }

extern "C" void kernel_launch(void* const* d_in, const int* in_sizes, int n_in,
                              void* d_out, int out_size) {
    const float* features = (const float*)d_in[0];   // [N,1024]
    const void*  edge_idx = d_in[1];                 // [2,E]
    const float* W1       = (const float*)d_in[2];   // [512,1024]
    const float* b1       = (const float*)d_in[3];
    const float* W2       = (const float*)d_in[4];   // [128,512]
    const float* b2       = (const float*)d_in[5];
    const float* b3       = (const float*)d_in[6];
    const float* b4       = (const float*)d_in[7];
    const float* head1    = (const float*)d_in[8];   // [128,128]

    const int n = in_sizes[0] / IN_DIM;
    const int e = in_sizes[1] / 2;

    float* out = (float*)d_out;
    float* z_out  = out;
    float* h2_out = out + (size_t)n * OUT_DIM;
    float* h4_out = out + (size_t)n * OUT_DIM * 2;

    const int TPB = 256;
    dim3 blk(256);
    int aggb = ceil_div(n * 32, TPB);

    // ---- CSR + norm preprocessing ----
    k_pre<<<ceil_div(n, TPB), TPB>>>((const int*)edge_idx, n);
    k_count<<<ceil_div(e, TPB), TPB>>>(edge_idx, e, n);
    k_dinv<<<ceil_div(n, TPB), TPB>>>(n);
    k_scan<<<1, 1024>>>(n);
    k_fill<<<ceil_div(e, TPB), TPB>>>(edge_idx, e, n);

    // ---- weight precomputes ----
    k_misc<<<6, 256>>>(W1, W2, b1, b3, head1);
    {
        dim3 grid(IN_DIM / 128, 2);
        k_w21<<<grid, blk>>>(W2, W1);
    }

    // ---- P = X @ W21^T [N,128] -> g_T (tf32) ----
    {
        dim3 grid(1, ceil_div(n, 64));
        k_mma<0, 3, 1, 0, 64><<<grid, blk>>>(n, OUT_DIM, IN_DIM, features, nullptr, nullptr, nullptr);
    }

    // ---- S1 = Ahat P -> g_H (also computes c) ; h2 = Ahat S1 + c(x)u2 + b2 ----
    k_agg<1, 2, 0, 1><<<aggb, blk>>>(nullptr, nullptr, nullptr, n);
    k_agg<2, 0, 1, 0><<<aggb, blk>>>(nullptr, h2_out, b2, n);

    // ---- z = h2 @ head1 -> z_out (tf32, B = head1^T) ----
    {
        dim3 grid(1, ceil_div(n, 64));
        k_mma<0, 5, 0, 0, 64><<<grid, blk>>>(n, OUT_DIM, OUT_DIM, h2_out, nullptr, z_out, nullptr);
    }

    // ---- S2 = Ahat z -> g_T ; Q = Ahat S2 -> g_H ----
    k_agg<0, 1, 0, 0><<<aggb, blk>>>(z_out, nullptr, nullptr, n);
    k_agg<1, 2, 0, 0><<<aggb, blk>>>(nullptr, nullptr, nullptr, n);

    // ---- h4 = Q @ W21 + c(x)u4 + b4 -> h4_out (tf32, B = W21t) ----
    {
        dim3 grid(IN_DIM / 128, ceil_div(n, 128));
        k_mma<2, 4, 0, 1, 128><<<grid, blk>>>(n, IN_DIM, OUT_DIM, nullptr, nullptr, h4_out, b4);
    }

    (void)n_in; (void)out_size;
}